// round 1
// baseline (speedup 1.0000x reference)
#include <cuda_runtime.h>
#include <math.h>

#define NN 100000
#define EE 1600000

// ---------------- scratch (static device globals; no allocs) ----------------
__device__ __align__(16) float g_gate[EE];
__device__ __align__(16) float g_norm[EE];
__device__ __align__(16) int   g_src[EE];
__device__ __align__(16) int   g_dst[EE];
__device__ __align__(16) float g_deg[NN];
__device__ __align__(16) float g_dinv[NN];
__device__ __align__(16) float g_tu[NN * 64];
__device__ __align__(16) float g_tv[NN * 64];
__device__ __align__(16) float g_xw[NN * 128];
__device__ __align__(16) float g_hh[NN * 128];
__device__ __align__(16) float g_x1[NN * 128];
__device__ int g_is32;

// ---------------- helpers ----------------
__device__ __forceinline__ void red_add_v4(float* addr, float4 v) {
    asm volatile("red.global.add.v4.f32 [%0], {%1,%2,%3,%4};"
                 :: "l"(addr), "f"(v.x), "f"(v.y), "f"(v.z), "f"(v.w)
                 : "memory");
}

// ---------------- detect edge_index dtype (int64 vs int32) ----------------
__global__ void k_detect(const long long* __restrict__ ei) {
    if (threadIdx.x == 0 && blockIdx.x == 0) {
        int bad = 0;
        for (int i = 0; i < 128; ++i) {
            long long v = ei[i];
            if (v < 0 || v >= (long long)NN) { bad = 1; break; }
        }
        g_is32 = bad;  // 1 -> data is really int32
    }
}

// ---------------- init degree with self-loop weight 1.0 ----------------
__global__ void k_init_deg() {
    int i = blockIdx.x * 256 + threadIdx.x;
    if (i < NN) g_deg[i] = 1.0f;
}

// ---------------- per-node gate precompute: tu = m @ W1[0:16], tv = m @ W1[16:32] ----------------
__global__ __launch_bounds__(128) void k_node_pre(const float* __restrict__ motif,
                                                  const float* __restrict__ w1) {
    __shared__ __align__(16) float sW[32 * 64];
    for (int i = threadIdx.x; i < 2048; i += 128) sW[i] = w1[i];
    __syncthreads();
    int n = blockIdx.x * 128 + threadIdx.x;
    if (n >= NN) return;
    float m[16];
    const float4* m4 = (const float4*)(motif + (size_t)n * 16);
#pragma unroll
    for (int q = 0; q < 4; ++q) {
        float4 v = m4[q];
        m[4*q] = v.x; m[4*q+1] = v.y; m[4*q+2] = v.z; m[4*q+3] = v.w;
    }
    float* tu = g_tu + (size_t)n * 64;
    float* tv = g_tv + (size_t)n * 64;
#pragma unroll 4
    for (int j = 0; j < 64; j += 4) {
        float4 a = make_float4(0.f, 0.f, 0.f, 0.f);
        float4 b = make_float4(0.f, 0.f, 0.f, 0.f);
#pragma unroll
        for (int k = 0; k < 16; ++k) {
            float4 wu = *(const float4*)&sW[k * 64 + j];
            float4 wv = *(const float4*)&sW[(16 + k) * 64 + j];
            a.x += m[k] * wu.x; a.y += m[k] * wu.y; a.z += m[k] * wu.z; a.w += m[k] * wu.w;
            b.x += m[k] * wv.x; b.y += m[k] * wv.y; b.z += m[k] * wv.z; b.w += m[k] * wv.w;
        }
        *(float4*)&tu[j] = a;
        *(float4*)&tv[j] = b;
    }
}

// ---------------- per-edge gate MLP + atomic degree accumulation ----------------
__global__ __launch_bounds__(256) void k_edge_gate(const long long* __restrict__ ei,
                                                   const float* __restrict__ motif,
                                                   const float* __restrict__ w1,
                                                   const float* __restrict__ b1,
                                                   const float* __restrict__ w2,
                                                   const float* __restrict__ b2) {
    // transposed so k (16) is contiguous: sC[j*16+k] = W1[32+k][j], sD[j*16+k] = W1[48+k][j]
    __shared__ __align__(16) float sC[1024];
    __shared__ __align__(16) float sD[1024];
    __shared__ __align__(16) float sB1[64];
    __shared__ __align__(16) float sW2[64];
    int tid = threadIdx.x;
    for (int i = tid; i < 1024; i += 256) {
        int j = i >> 4, k = i & 15;
        sC[i] = w1[(32 + k) * 64 + j];
        sD[i] = w1[(48 + k) * 64 + j];
    }
    if (tid < 64) { sB1[tid] = b1[tid]; sW2[tid] = w2[tid]; }
    __syncthreads();

    int e = blockIdx.x * 256 + tid;
    if (e >= EE) return;

    int s, d;
    if (g_is32) {
        const int* e32 = (const int*)ei;
        s = e32[e]; d = e32[EE + e];
    } else {
        s = (int)ei[e]; d = (int)ei[EE + e];
    }

    float dm[16], pm[16];
    const float4* mu4 = (const float4*)(motif + (size_t)s * 16);
    const float4* mv4 = (const float4*)(motif + (size_t)d * 16);
#pragma unroll
    for (int q = 0; q < 4; ++q) {
        float4 a = mu4[q], b = mv4[q];
        dm[4*q]   = fabsf(a.x - b.x); pm[4*q]   = a.x * b.x;
        dm[4*q+1] = fabsf(a.y - b.y); pm[4*q+1] = a.y * b.y;
        dm[4*q+2] = fabsf(a.z - b.z); pm[4*q+2] = a.z * b.z;
        dm[4*q+3] = fabsf(a.w - b.w); pm[4*q+3] = a.w * b.w;
    }

    const float4* tu = (const float4*)(g_tu + (size_t)s * 64);
    const float4* tv = (const float4*)(g_tv + (size_t)d * 64);
    float g = 0.f;
#pragma unroll 2
    for (int j4 = 0; j4 < 16; ++j4) {
        float4 u = tu[j4], v = tv[j4];
        float4 bb = *(const float4*)&sB1[j4 * 4];
        float4 ww = *(const float4*)&sW2[j4 * 4];
        float hj[4] = { u.x + v.x + bb.x, u.y + v.y + bb.y,
                        u.z + v.z + bb.z, u.w + v.w + bb.w };
#pragma unroll
        for (int jj = 0; jj < 4; ++jj) {
            int j = j4 * 4 + jj;
            const float4* c4 = (const float4*)&sC[j * 16];
            const float4* d4 = (const float4*)&sD[j * 16];
            float acc = hj[jj];
#pragma unroll
            for (int k4 = 0; k4 < 4; ++k4) {
                float4 c = c4[k4], dd = d4[k4];
                acc += dm[k4*4+0] * c.x + pm[k4*4+0] * dd.x;
                acc += dm[k4*4+1] * c.y + pm[k4*4+1] * dd.y;
                acc += dm[k4*4+2] * c.z + pm[k4*4+2] * dd.z;
                acc += dm[k4*4+3] * c.w + pm[k4*4+3] * dd.w;
            }
            hj[jj] = fmaxf(acc, 0.f);
        }
        g += hj[0] * ww.x + hj[1] * ww.y + hj[2] * ww.z + hj[3] * ww.w;
    }
    g += b2[0];
    float gate = 1.f / (1.f + expf(-g));
    g_gate[e] = gate;
    g_src[e] = s;
    g_dst[e] = d;
    atomicAdd(&g_deg[d], gate);
}

// ---------------- dinv = deg^-0.5 (deg >= 1 always, self-loops) ----------------
__global__ void k_dinv() {
    int i = blockIdx.x * 256 + threadIdx.x;
    if (i < NN) g_dinv[i] = rsqrtf(g_deg[i]);
}

// ---------------- per-edge norm ----------------
__global__ void k_edge_norm() {
    int e = blockIdx.x * 256 + threadIdx.x;
    if (e < EE) g_norm[e] = g_dinv[g_src[e]] * g_gate[e] * g_dinv[g_dst[e]];
}

// ---------------- SGEMM: C[M,NC] = A[M,128] @ B[128,NC] (+bias) ----------------
template <int NC, bool ADD_BIAS>
__global__ __launch_bounds__(256) void k_gemm(const float* __restrict__ A,
                                              const float* __restrict__ B,
                                              const float* __restrict__ bias,
                                              float* __restrict__ C, int M) {
    constexpr int BM = 64, BK = 16;
    constexpr int NTX = NC / 4;       // threads along N
    constexpr int NTY = 256 / NTX;    // threads along M
    constexpr int TM = BM / NTY;      // rows per thread (8 for NC=128, 4 for NC=64)
    constexpr int TN = 4;

    __shared__ __align__(16) float As[BK][BM + 4];
    __shared__ __align__(16) float Bs[BK][NC];

    int tid = threadIdx.x;
    int tx = tid % NTX, ty = tid / NTX;
    int rowBase = blockIdx.x * BM;

    float acc[TM][TN];
#pragma unroll
    for (int m = 0; m < TM; ++m)
#pragma unroll
        for (int n = 0; n < TN; ++n) acc[m][n] = 0.f;

    int ar = tid >> 2;           // 0..63
    int ak = (tid & 3) * 4;      // 0,4,8,12

    for (int k0 = 0; k0 < 128; k0 += BK) {
        float4 av = make_float4(0.f, 0.f, 0.f, 0.f);
        int grow = rowBase + ar;
        if (grow < M) av = *(const float4*)(A + (size_t)grow * 128 + k0 + ak);
        As[ak + 0][ar] = av.x; As[ak + 1][ar] = av.y;
        As[ak + 2][ar] = av.z; As[ak + 3][ar] = av.w;
#pragma unroll
        for (int i = 0; i < (BK * NC) / (256 * 4); ++i) {
            int idx = tid + i * 256;
            int br = (idx * 4) / NC;
            int bc = (idx * 4) % NC;
            *(float4*)&Bs[br][bc] = *(const float4*)(B + (size_t)(k0 + br) * NC + bc);
        }
        __syncthreads();
#pragma unroll
        for (int k = 0; k < BK; ++k) {
            float4 bq = *(const float4*)&Bs[k][tx * 4];
            float bf[TN] = { bq.x, bq.y, bq.z, bq.w };
            float af[TM];
#pragma unroll
            for (int m = 0; m < TM; m += 4) {
                float4 a = *(const float4*)&As[k][ty * TM + m];
                af[m] = a.x; af[m + 1] = a.y; af[m + 2] = a.z; af[m + 3] = a.w;
            }
#pragma unroll
            for (int m = 0; m < TM; ++m)
#pragma unroll
                for (int n = 0; n < TN; ++n) acc[m][n] += af[m] * bf[n];
        }
        __syncthreads();
    }

#pragma unroll
    for (int m = 0; m < TM; ++m) {
        int r = rowBase + ty * TM + m;
        if (r < M) {
            float4 v = make_float4(acc[m][0], acc[m][1], acc[m][2], acc[m][3]);
            if (ADD_BIAS) {
                v.x += bias[tx * 4 + 0]; v.y += bias[tx * 4 + 1];
                v.z += bias[tx * 4 + 2]; v.w += bias[tx * 4 + 3];
            }
            *(float4*)(C + (size_t)r * NC + tx * 4) = v;
        }
    }
}

// ---------------- hh init with self-loop contribution: hh = dinv^2 * xw ----------------
__global__ void k_init_hh() {
    int i = blockIdx.x * 256 + threadIdx.x;  // float4 index over N*32
    if (i >= NN * 32) return;
    int n = i >> 5;
    float w = g_dinv[n];
    w = w * w;
    float4 v = ((const float4*)g_xw)[i];
    v.x *= w; v.y *= w; v.z *= w; v.w *= w;
    ((float4*)g_hh)[i] = v;
}

// ---------------- scatter: hh[dst] += norm * xw[src], one warp/edge ----------------
__global__ __launch_bounds__(256) void k_scatter() {
    int w = (blockIdx.x * 256 + threadIdx.x) >> 5;
    int lane = threadIdx.x & 31;
    if (w >= EE) return;
    float nrm = g_norm[w];
    int s = g_src[w], d = g_dst[w];
    float4 v = *(const float4*)(g_xw + (size_t)s * 128 + lane * 4);
    v.x *= nrm; v.y *= nrm; v.z *= nrm; v.w *= nrm;
    red_add_v4(g_hh + (size_t)d * 128 + lane * 4, v);
}

// ---------------- bias + LayerNorm + relu + residual, one warp/node ----------------
__global__ __launch_bounds__(256) void k_ln_res(const float* __restrict__ xin,
                                                float* __restrict__ xout,
                                                const float* __restrict__ cb,
                                                const float* __restrict__ lg,
                                                const float* __restrict__ lb) {
    int w = (blockIdx.x * 256 + threadIdx.x) >> 5;
    int lane = threadIdx.x & 31;
    if (w >= NN) return;
    float4 h = *(const float4*)(g_hh + (size_t)w * 128 + lane * 4);
    float4 b = *(const float4*)(cb + lane * 4);
    h.x += b.x; h.y += b.y; h.z += b.z; h.w += b.w;
    float s = h.x + h.y + h.z + h.w;
#pragma unroll
    for (int o = 16; o; o >>= 1) s += __shfl_xor_sync(0xffffffffu, s, o);
    float mean = s * 0.0078125f;
    float d0 = h.x - mean, d1 = h.y - mean, d2 = h.z - mean, d3 = h.w - mean;
    float ss = d0 * d0 + d1 * d1 + d2 * d2 + d3 * d3;
#pragma unroll
    for (int o = 16; o; o >>= 1) ss += __shfl_xor_sync(0xffffffffu, ss, o);
    float inv = rsqrtf(ss * 0.0078125f + 1e-5f);
    float4 g = *(const float4*)(lg + lane * 4);
    float4 bb = *(const float4*)(lb + lane * 4);
    float4 xi = *(const float4*)(xin + (size_t)w * 128 + lane * 4);
    float4 o4;
    o4.x = xi.x + fmaxf(d0 * inv * g.x + bb.x, 0.f);
    o4.y = xi.y + fmaxf(d1 * inv * g.y + bb.y, 0.f);
    o4.z = xi.z + fmaxf(d2 * inv * g.z + bb.z, 0.f);
    o4.w = xi.w + fmaxf(d3 * inv * g.w + bb.w, 0.f);
    *(float4*)(xout + (size_t)w * 128 + lane * 4) = o4;
}

// ---------------- orchestration ----------------
extern "C" void kernel_launch(void* const* d_in, const int* in_sizes, int n_in,
                              void* d_out, int out_size) {
    const float*     x     = (const float*)d_in[0];
    const float*     motif = (const float*)d_in[1];
    const long long* ei    = (const long long*)d_in[2];
    const float*     gw1   = (const float*)d_in[3];
    const float*     gb1   = (const float*)d_in[4];
    const float*     gw2   = (const float*)d_in[5];
    const float*     gb2   = (const float*)d_in[6];
    const float*     cw    = (const float*)d_in[7];
    const float*     cb    = (const float*)d_in[8];
    const float*     lg    = (const float*)d_in[9];
    const float*     lb    = (const float*)d_in[10];
    const float*     hw    = (const float*)d_in[11];
    const float*     hb    = (const float*)d_in[12];
    float* out = (float*)d_out;

    float *x1p, *xwp;
    cudaGetSymbolAddress((void**)&x1p, g_x1);
    cudaGetSymbolAddress((void**)&xwp, g_xw);

    k_detect<<<1, 32>>>(ei);
    k_init_deg<<<(NN + 255) / 256, 256>>>();
    k_node_pre<<<(NN + 127) / 128, 128>>>(motif, gw1);
    k_edge_gate<<<EE / 256, 256>>>(ei, motif, gw1, gb1, gw2, gb2);
    k_dinv<<<(NN + 255) / 256, 256>>>();
    k_edge_norm<<<EE / 256, 256>>>();

    for (int i = 0; i < 2; ++i) {
        const float* xin = (i == 0) ? x : x1p;
        k_gemm<128, false><<<(NN + 63) / 64, 256>>>(xin, cw + i * 128 * 128, nullptr, xwp, NN);
        k_init_hh<<<(NN * 32 + 255) / 256, 256>>>();
        k_scatter<<<EE / 8, 256>>>();
        k_ln_res<<<(NN + 7) / 8, 256>>>(xin, x1p, cb + i * 128, lg + i * 128, lb + i * 128);
    }
    k_gemm<64, true><<<(NN + 63) / 64, 256>>>(x1p, hw, hb, out, NN);
}

// round 4
// speedup vs baseline: 1.4030x; 1.4030x over previous
#include <cuda_runtime.h>
#include <math.h>

#define NN 100000
#define EE 1600000
#define NB_SCAN 98   // ceil(NN/1024)

// ---------------- scratch (static device globals; no allocs) ----------------
__device__ __align__(16) float g_gate[EE];
__device__ __align__(16) int   g_src[EE];
__device__ __align__(16) int   g_dst[EE];
__device__ __align__(16) int   g_csr_src[EE];
__device__ __align__(16) float g_csr_norm[EE];
__device__ __align__(16) float g_deg[NN];
__device__ __align__(16) float g_dinv[NN];
__device__ __align__(16) int   g_cnt[NN];
__device__ __align__(16) int   g_tmp[NN];
__device__ __align__(16) int   g_rowptr[NN + 1];
__device__ __align__(16) int   g_cursor[NN];
__device__ __align__(16) int   g_bsum[NB_SCAN];
__device__ __align__(16) int   g_bsum2[NB_SCAN];
__device__ __align__(16) float g_tu[NN * 64];
__device__ __align__(16) float g_tv[NN * 64];
__device__ __align__(16) float g_xw[NN * 128];
__device__ __align__(16) float g_x1[NN * 128];
__device__ int g_is32;

// ---------------- detect edge_index dtype (int64 vs int32) ----------------
__global__ void k_detect(const long long* __restrict__ ei) {
    if (threadIdx.x == 0 && blockIdx.x == 0) {
        int bad = 0;
        for (int i = 0; i < 128; ++i) {
            long long v = ei[i];
            if (v < 0 || v >= (long long)NN) { bad = 1; break; }
        }
        g_is32 = bad;
    }
}

// ---------------- init degree (self loop weight 1.0) and counts ----------------
__global__ void k_init() {
    int i = blockIdx.x * 256 + threadIdx.x;
    if (i < NN) { g_deg[i] = 1.0f; g_cnt[i] = 0; }
}

// ---------------- per-node gate precompute: tu = m @ W1[0:16], tv = m @ W1[16:32] ----------------
__global__ __launch_bounds__(128) void k_node_pre(const float* __restrict__ motif,
                                                  const float* __restrict__ w1) {
    __shared__ __align__(16) float sW[32 * 64];
    for (int i = threadIdx.x; i < 2048; i += 128) sW[i] = w1[i];
    __syncthreads();
    int n = blockIdx.x * 128 + threadIdx.x;
    if (n >= NN) return;
    float m[16];
    const float4* m4 = (const float4*)(motif + (size_t)n * 16);
#pragma unroll
    for (int q = 0; q < 4; ++q) {
        float4 v = m4[q];
        m[4*q] = v.x; m[4*q+1] = v.y; m[4*q+2] = v.z; m[4*q+3] = v.w;
    }
    float* tu = g_tu + (size_t)n * 64;
    float* tv = g_tv + (size_t)n * 64;
#pragma unroll 4
    for (int j = 0; j < 64; j += 4) {
        float4 a = make_float4(0.f, 0.f, 0.f, 0.f);
        float4 b = make_float4(0.f, 0.f, 0.f, 0.f);
#pragma unroll
        for (int k = 0; k < 16; ++k) {
            float4 wu = *(const float4*)&sW[k * 64 + j];
            float4 wv = *(const float4*)&sW[(16 + k) * 64 + j];
            a.x += m[k] * wu.x; a.y += m[k] * wu.y; a.z += m[k] * wu.z; a.w += m[k] * wu.w;
            b.x += m[k] * wv.x; b.y += m[k] * wv.y; b.z += m[k] * wv.z; b.w += m[k] * wv.w;
        }
        *(float4*)&tu[j] = a;
        *(float4*)&tv[j] = b;
    }
}

// ---------------- warp-per-edge gate MLP; weights in registers ----------------
__global__ __launch_bounds__(256) void k_edge_gate(const long long* __restrict__ ei,
                                                   const float* __restrict__ motif,
                                                   const float* __restrict__ w1,
                                                   const float* __restrict__ b1,
                                                   const float* __restrict__ w2,
                                                   const float* __restrict__ b2) {
    int lane = threadIdx.x & 31;
    int warpId = (blockIdx.x * 256 + threadIdx.x) >> 5;
    int nWarps = (gridDim.x * 256) >> 5;
    int j0 = lane, j1 = lane + 32;

    float c0[16], c1[16], d0r[16], d1r[16];
#pragma unroll
    for (int k = 0; k < 16; ++k) {
        c0[k]  = w1[(32 + k) * 64 + j0];
        c1[k]  = w1[(32 + k) * 64 + j1];
        d0r[k] = w1[(48 + k) * 64 + j0];
        d1r[k] = w1[(48 + k) * 64 + j1];
    }
    float b10 = b1[j0], b11 = b1[j1];
    float w20 = w2[j0], w21 = w2[j1];
    float b2s = b2[0];
    int is32 = g_is32;
    const int* e32 = (const int*)ei;

    for (int e = warpId; e < EE; e += nWarps) {
        int s, d;
        if (is32) { s = e32[e]; d = e32[EE + e]; }
        else      { s = (int)ei[e]; d = (int)ei[EE + e]; }

        float dm[16], pm[16];
        const float4* mu4 = (const float4*)(motif + (size_t)s * 16);
        const float4* mv4 = (const float4*)(motif + (size_t)d * 16);
#pragma unroll
        for (int q = 0; q < 4; ++q) {
            float4 a = mu4[q], b = mv4[q];
            dm[4*q]   = fabsf(a.x - b.x); pm[4*q]   = a.x * b.x;
            dm[4*q+1] = fabsf(a.y - b.y); pm[4*q+1] = a.y * b.y;
            dm[4*q+2] = fabsf(a.z - b.z); pm[4*q+2] = a.z * b.z;
            dm[4*q+3] = fabsf(a.w - b.w); pm[4*q+3] = a.w * b.w;
        }

        float h0 = g_tu[(size_t)s * 64 + j0] + g_tv[(size_t)d * 64 + j0] + b10;
        float h1 = g_tu[(size_t)s * 64 + j1] + g_tv[(size_t)d * 64 + j1] + b11;
#pragma unroll
        for (int k = 0; k < 16; ++k) {
            h0 += dm[k] * c0[k] + pm[k] * d0r[k];
            h1 += dm[k] * c1[k] + pm[k] * d1r[k];
        }
        h0 = fmaxf(h0, 0.f); h1 = fmaxf(h1, 0.f);
        float gp = h0 * w20 + h1 * w21;
#pragma unroll
        for (int o = 16; o; o >>= 1) gp += __shfl_xor_sync(0xffffffffu, gp, o);

        if (lane == 0) {
            float gate = 1.f / (1.f + expf(-(gp + b2s)));
            g_gate[e] = gate;
            g_src[e] = s;
            g_dst[e] = d;
            atomicAdd(&g_deg[d], gate);
            atomicAdd(&g_cnt[d], 1);
        }
    }
}

// ---------------- prefix scan of counts -> row_ptr (3 kernels) ----------------
__global__ __launch_bounds__(1024) void k_scan1() {
    __shared__ int sh[1024];
    int t = threadIdx.x;
    int i = blockIdx.x * 1024 + t;
    int v = (i < NN) ? g_cnt[i] : 0;
    sh[t] = v; __syncthreads();
#pragma unroll
    for (int off = 1; off < 1024; off <<= 1) {
        int x = (t >= off) ? sh[t - off] : 0;
        __syncthreads();
        sh[t] += x;
        __syncthreads();
    }
    if (i < NN) g_tmp[i] = sh[t];
    if (t == 1023) g_bsum[blockIdx.x] = sh[1023];
}

__global__ __launch_bounds__(128) void k_scan2() {
    __shared__ int sh[128];
    int t = threadIdx.x;
    int v = (t < NB_SCAN) ? g_bsum[t] : 0;
    sh[t] = v; __syncthreads();
#pragma unroll
    for (int off = 1; off < 128; off <<= 1) {
        int x = (t >= off) ? sh[t - off] : 0;
        __syncthreads();
        sh[t] += x;
        __syncthreads();
    }
    if (t < NB_SCAN) g_bsum2[t] = sh[t];
}

__global__ void k_scan3() {
    int i = blockIdx.x * 256 + threadIdx.x;
    if (i >= NN) return;
    int b = i >> 10;
    int off = b ? g_bsum2[b - 1] : 0;
    int excl = g_tmp[i] - g_cnt[i] + off;
    g_rowptr[i] = excl;
    g_cursor[i] = excl;
    if (i == 0) g_rowptr[NN] = EE;
}

// ---------------- dinv ----------------
__global__ void k_dinv() {
    int i = blockIdx.x * 256 + threadIdx.x;
    if (i < NN) g_dinv[i] = rsqrtf(g_deg[i]);
}

// ---------------- fill CSR (norm + src, bucketed by dst) ----------------
__global__ void k_fill() {
    int e = blockIdx.x * 256 + threadIdx.x;
    if (e >= EE) return;
    int s = g_src[e], d = g_dst[e];
    float nrm = g_dinv[s] * g_gate[e] * g_dinv[d];
    int p = atomicAdd(&g_cursor[d], 1);
    g_csr_src[p] = s;
    g_csr_norm[p] = nrm;
}

// ---------------- SGEMM: C[M,BN] = A[M,128] @ B[128,BN] (+bias) ----------------
template <int BN, bool ADD_BIAS>
__global__ __launch_bounds__(256) void k_gemm2(const float* __restrict__ A,
                                               const float* __restrict__ B,
                                               const float* __restrict__ bias,
                                               float* __restrict__ C, int M) {
    constexpr int TN = BN / 16;   // 8 for 128, 4 for 64
    __shared__ __align__(16) float As[16][132];
    __shared__ __align__(16) float Bs[16][BN];

    int tid = threadIdx.x;
    int tx = tid & 15, ty = tid >> 4;
    int rowBase = blockIdx.x * 128;

    float acc[8][TN];
#pragma unroll
    for (int m = 0; m < 8; ++m)
#pragma unroll
        for (int n = 0; n < TN; ++n) acc[m][n] = 0.f;

    int ar = tid >> 1;            // 0..127
    int ak = (tid & 1) * 8;       // 0 or 8

    for (int k0 = 0; k0 < 128; k0 += 16) {
        float4 a0 = make_float4(0.f,0.f,0.f,0.f), a1 = a0;
        int grow = rowBase + ar;
        if (grow < M) {
            a0 = *(const float4*)(A + (size_t)grow * 128 + k0 + ak);
            a1 = *(const float4*)(A + (size_t)grow * 128 + k0 + ak + 4);
        }
        As[ak + 0][ar] = a0.x; As[ak + 1][ar] = a0.y;
        As[ak + 2][ar] = a0.z; As[ak + 3][ar] = a0.w;
        As[ak + 4][ar] = a1.x; As[ak + 5][ar] = a1.y;
        As[ak + 6][ar] = a1.z; As[ak + 7][ar] = a1.w;

        if (BN == 128) {
            int br = tid >> 5, bc = (tid & 31) * 4;
            *(float4*)&Bs[br][bc]     = *(const float4*)(B + (size_t)(k0 + br) * BN + bc);
            *(float4*)&Bs[br + 8][bc] = *(const float4*)(B + (size_t)(k0 + br + 8) * BN + bc);
        } else {
            int br = tid >> 4, bc = (tid & 15) * 4;
            *(float4*)&Bs[br][bc] = *(const float4*)(B + (size_t)(k0 + br) * BN + bc);
        }
        __syncthreads();

#pragma unroll
        for (int k = 0; k < 16; ++k) {
            float a[8], bb[TN];
            float4 av0 = *(const float4*)&As[k][ty * 4];
            float4 av1 = *(const float4*)&As[k][ty * 4 + 64];
            a[0]=av0.x; a[1]=av0.y; a[2]=av0.z; a[3]=av0.w;
            a[4]=av1.x; a[5]=av1.y; a[6]=av1.z; a[7]=av1.w;
            float4 bv0 = *(const float4*)&Bs[k][tx * 4];
            bb[0]=bv0.x; bb[1]=bv0.y; bb[2]=bv0.z; bb[3]=bv0.w;
            if (TN == 8) {
                float4 bv1 = *(const float4*)&Bs[k][tx * 4 + 64];
                bb[4]=bv1.x; bb[5]=bv1.y; bb[6]=bv1.z; bb[7]=bv1.w;
            }
#pragma unroll
            for (int m = 0; m < 8; ++m)
#pragma unroll
                for (int n = 0; n < TN; ++n) acc[m][n] += a[m] * bb[n];
        }
        __syncthreads();
    }

#pragma unroll
    for (int m = 0; m < 8; ++m) {
        int r = rowBase + ty * 4 + ((m < 4) ? m : (64 + m - 4));
        if (r < M) {
            float4 v = make_float4(acc[m][0], acc[m][1], acc[m][2], acc[m][3]);
            if (ADD_BIAS) {
                v.x += bias[tx*4+0]; v.y += bias[tx*4+1];
                v.z += bias[tx*4+2]; v.w += bias[tx*4+3];
            }
            *(float4*)(C + (size_t)r * BN + tx * 4) = v;
            if (TN == 8) {
                float4 v2 = make_float4(acc[m][4], acc[m][5], acc[m][6], acc[m][7]);
                if (ADD_BIAS) {
                    v2.x += bias[tx*4+64]; v2.y += bias[tx*4+65];
                    v2.z += bias[tx*4+66]; v2.w += bias[tx*4+67];
                }
                *(float4*)(C + (size_t)r * BN + tx * 4 + 64) = v2;
            }
        }
    }
}

// ---------------- fused aggregate + bias + LN + relu + residual (warp/node) ----------------
__global__ __launch_bounds__(256) void k_agg(const float* __restrict__ xin,
                                             float* __restrict__ xout,
                                             const float* __restrict__ cb,
                                             const float* __restrict__ lg,
                                             const float* __restrict__ lb) {
    int w = (blockIdx.x * 256 + threadIdx.x) >> 5;
    int lane = threadIdx.x & 31;
    if (w >= NN) return;

    int base = g_rowptr[w], end = g_rowptr[w + 1];
    float di = g_dinv[w];
    float sw = di * di;
    float4 acc = *(const float4*)(g_xw + (size_t)w * 128 + lane * 4);
    acc.x *= sw; acc.y *= sw; acc.z *= sw; acc.w *= sw;

    int i = base, s = 0;
    float nrm = 0.f;
    if (i < end) { s = g_csr_src[i]; nrm = g_csr_norm[i]; }
    while (i < end) {
        float4 v = *(const float4*)(g_xw + (size_t)s * 128 + lane * 4);
        int i2 = i + 1, s2 = 0;
        float n2 = 0.f;
        if (i2 < end) { s2 = g_csr_src[i2]; n2 = g_csr_norm[i2]; }
        acc.x += nrm * v.x; acc.y += nrm * v.y;
        acc.z += nrm * v.z; acc.w += nrm * v.w;
        i = i2; s = s2; nrm = n2;
    }

    float4 b = *(const float4*)(cb + lane * 4);
    acc.x += b.x; acc.y += b.y; acc.z += b.z; acc.w += b.w;

    float ssum = acc.x + acc.y + acc.z + acc.w;
#pragma unroll
    for (int o = 16; o; o >>= 1) ssum += __shfl_xor_sync(0xffffffffu, ssum, o);
    float mean = ssum * 0.0078125f;
    float d0 = acc.x - mean, d1 = acc.y - mean, d2 = acc.z - mean, d3 = acc.w - mean;
    float ss = d0*d0 + d1*d1 + d2*d2 + d3*d3;
#pragma unroll
    for (int o = 16; o; o >>= 1) ss += __shfl_xor_sync(0xffffffffu, ss, o);
    float inv = rsqrtf(ss * 0.0078125f + 1e-5f);

    float4 g = *(const float4*)(lg + lane * 4);
    float4 bb = *(const float4*)(lb + lane * 4);
    float4 xi = *(const float4*)(xin + (size_t)w * 128 + lane * 4);
    float4 o4;
    o4.x = xi.x + fmaxf(d0 * inv * g.x + bb.x, 0.f);
    o4.y = xi.y + fmaxf(d1 * inv * g.y + bb.y, 0.f);
    o4.z = xi.z + fmaxf(d2 * inv * g.z + bb.z, 0.f);
    o4.w = xi.w + fmaxf(d3 * inv * g.w + bb.w, 0.f);
    *(float4*)(xout + (size_t)w * 128 + lane * 4) = o4;
}

// ---------------- orchestration ----------------
extern "C" void kernel_launch(void* const* d_in, const int* in_sizes, int n_in,
                              void* d_out, int out_size) {
    const float*     x     = (const float*)d_in[0];
    const float*     motif = (const float*)d_in[1];
    const long long* ei    = (const long long*)d_in[2];
    const float*     gw1   = (const float*)d_in[3];
    const float*     gb1   = (const float*)d_in[4];
    const float*     gw2   = (const float*)d_in[5];
    const float*     gb2   = (const float*)d_in[6];
    const float*     cw    = (const float*)d_in[7];
    const float*     cb    = (const float*)d_in[8];
    const float*     lg    = (const float*)d_in[9];
    const float*     lb    = (const float*)d_in[10];
    const float*     hw    = (const float*)d_in[11];
    const float*     hb    = (const float*)d_in[12];
    float* out = (float*)d_out;

    float *x1p, *xwp;
    cudaGetSymbolAddress((void**)&x1p, g_x1);
    cudaGetSymbolAddress((void**)&xwp, g_xw);

    k_detect<<<1, 32>>>(ei);
    k_init<<<(NN + 255) / 256, 256>>>();
    k_node_pre<<<(NN + 127) / 128, 128>>>(motif, gw1);
    k_edge_gate<<<1480, 256>>>(ei, motif, gw1, gb1, gw2, gb2);
    k_scan1<<<NB_SCAN, 1024>>>();
    k_scan2<<<1, 128>>>();
    k_scan3<<<(NN + 255) / 256, 256>>>();
    k_dinv<<<(NN + 255) / 256, 256>>>();
    k_fill<<<EE / 256, 256>>>();

    for (int i = 0; i < 2; ++i) {
        const float* xin = (i == 0) ? x : x1p;
        k_gemm2<128, false><<<(NN + 127) / 128, 256>>>(xin, cw + i * 128 * 128, nullptr, xwp, NN);
        k_agg<<<(NN + 7) / 8, 256>>>(xin, x1p, cb + i * 128, lg + i * 128, lb + i * 128);
    }
    k_gemm2<64, true><<<(NN + 127) / 128, 256>>>(x1p, hw, hb, out, NN);
}

// round 6
// speedup vs baseline: 2.2720x; 1.6195x over previous
#include <cuda_runtime.h>
#include <math.h>

#define NN 100000
#define EE 1600000
#define NB_SCAN 98   // ceil(NN/1024)
#define NTILES (EE / 64)

// ---------------- scratch (static device globals; no allocs) ----------------
__device__ __align__(16) float g_gate[EE];
__device__ __align__(16) int   g_src[EE];
__device__ __align__(16) int   g_dst[EE];
__device__ __align__(16) int   g_csr_src[EE];
__device__ __align__(16) float g_csr_norm[EE];
__device__ __align__(16) float g_deg[NN];
__device__ __align__(16) float g_dinv[NN];
__device__ __align__(16) int   g_cnt[NN];
__device__ __align__(16) int   g_tmp[NN];
__device__ __align__(16) int   g_rowptr[NN + 1];
__device__ __align__(16) int   g_cursor[NN];
__device__ __align__(16) int   g_bsum[NB_SCAN];
__device__ __align__(16) int   g_bsum2[NB_SCAN];
__device__ __align__(16) float g_tu[NN * 64];
__device__ __align__(16) float g_tv[NN * 64];
__device__ __align__(16) float g_xw[NN * 128];
__device__ __align__(16) float g_x1[NN * 128];
__device__ int g_is32;

// ---------------- detect edge_index dtype (int64 vs int32) ----------------
__global__ void k_detect(const long long* __restrict__ ei) {
    if (threadIdx.x == 0 && blockIdx.x == 0) {
        int bad = 0;
        for (int i = 0; i < 128; ++i) {
            long long v = ei[i];
            if (v < 0 || v >= (long long)NN) { bad = 1; break; }
        }
        g_is32 = bad;
    }
}

// ---------------- init degree (self loop weight 1.0) and counts ----------------
__global__ void k_init() {
    int i = blockIdx.x * 256 + threadIdx.x;
    if (i < NN) { g_deg[i] = 1.0f; g_cnt[i] = 0; }
}

// ---------------- per-node gate precompute: tu = m @ W1[0:16], tv = m @ W1[16:32] ----------------
__global__ __launch_bounds__(128) void k_node_pre(const float* __restrict__ motif,
                                                  const float* __restrict__ w1) {
    __shared__ __align__(16) float sW[32 * 64];
    for (int i = threadIdx.x; i < 2048; i += 128) sW[i] = w1[i];
    __syncthreads();
    int n = blockIdx.x * 128 + threadIdx.x;
    if (n >= NN) return;
    float m[16];
    const float4* m4 = (const float4*)(motif + (size_t)n * 16);
#pragma unroll
    for (int q = 0; q < 4; ++q) {
        float4 v = m4[q];
        m[4*q] = v.x; m[4*q+1] = v.y; m[4*q+2] = v.z; m[4*q+3] = v.w;
    }
    float* tu = g_tu + (size_t)n * 64;
    float* tv = g_tv + (size_t)n * 64;
#pragma unroll 4
    for (int j = 0; j < 64; j += 4) {
        float4 a = make_float4(0.f, 0.f, 0.f, 0.f);
        float4 b = make_float4(0.f, 0.f, 0.f, 0.f);
#pragma unroll
        for (int k = 0; k < 16; ++k) {
            float4 wu = *(const float4*)&sW[k * 64 + j];
            float4 wv = *(const float4*)&sW[(16 + k) * 64 + j];
            a.x += m[k] * wu.x; a.y += m[k] * wu.y; a.z += m[k] * wu.z; a.w += m[k] * wu.w;
            b.x += m[k] * wv.x; b.y += m[k] * wv.y; b.z += m[k] * wv.z; b.w += m[k] * wv.w;
        }
        *(float4*)&tu[j] = a;
        *(float4*)&tv[j] = b;
    }
}

// ---------------- gate MLP as tiled GEMM: 64 edges/tile, [64x32]@[32x64] ----------------
__global__ __launch_bounds__(256) void k_edge_gate(const long long* __restrict__ ei,
                                                   const float* __restrict__ motif,
                                                   const float* __restrict__ w1,
                                                   const float* __restrict__ b1,
                                                   const float* __restrict__ w2,
                                                   const float* __restrict__ b2) {
    __shared__ __align__(16) float sW[32 * 64];   // W1 rows 32..63, [k][j]
    __shared__ __align__(16) float sF[32 * 68];   // feats [k][edge], padded stride 68

    int tid = threadIdx.x;
    int tx = tid & 15;        // hidden group (j = tx*4 .. tx*4+3)
    int ty = tid >> 4;        // edge group  (e = ty*4 .. ty*4+3)

    for (int i = tid; i < 2048; i += 256) sW[i] = w1[2048 + i];

    float b1r[4], w2r[4];
#pragma unroll
    for (int n = 0; n < 4; ++n) { b1r[n] = b1[tx * 4 + n]; w2r[n] = w2[tx * 4 + n]; }
    float b2s = b2[0];
    int is32 = g_is32;
    const int* e32 = (const int*)ei;

    int ge = tid >> 2;        // edge slot 0..63 for gather phase
    int q  = tid & 3;         // quarter of the 16 motif dims

    for (int tile = blockIdx.x; tile < NTILES; tile += gridDim.x) {
        int eBase = tile * 64;

        // ---- build feats tile: dm rows 0..15, pm rows 16..31 ----
        {
            int e = eBase + ge;
            int s, d;
            if (is32) { s = e32[e]; d = e32[EE + e]; }
            else      { s = (int)ei[e]; d = (int)ei[EE + e]; }
            float4 a = *(const float4*)(motif + (size_t)s * 16 + q * 4);
            float4 b = *(const float4*)(motif + (size_t)d * 16 + q * 4);
            int k0 = q * 4;
            sF[(k0 + 0) * 68 + ge] = fabsf(a.x - b.x);
            sF[(k0 + 1) * 68 + ge] = fabsf(a.y - b.y);
            sF[(k0 + 2) * 68 + ge] = fabsf(a.z - b.z);
            sF[(k0 + 3) * 68 + ge] = fabsf(a.w - b.w);
            sF[(16 + k0 + 0) * 68 + ge] = a.x * b.x;
            sF[(16 + k0 + 1) * 68 + ge] = a.y * b.y;
            sF[(16 + k0 + 2) * 68 + ge] = a.z * b.z;
            sF[(16 + k0 + 3) * 68 + ge] = a.w * b.w;
        }
        __syncthreads();

        // ---- GEMM: acc[edge 4][hidden 4] ----
        float acc[4][4];
#pragma unroll
        for (int i = 0; i < 4; ++i)
#pragma unroll
            for (int n = 0; n < 4; ++n) acc[i][n] = 0.f;

#pragma unroll
        for (int k = 0; k < 32; ++k) {
            float4 af = *(const float4*)&sF[k * 68 + ty * 4];
            float4 bf = *(const float4*)&sW[k * 64 + tx * 4];
            float a[4] = { af.x, af.y, af.z, af.w };
            float b[4] = { bf.x, bf.y, bf.z, bf.w };
#pragma unroll
            for (int i = 0; i < 4; ++i)
#pragma unroll
                for (int n = 0; n < 4; ++n) acc[i][n] += a[i] * b[n];
        }

        // ---- epilogue: + tu[s] + tv[d] + b1, relu, dot w2, reduce over tx ----
        float gp[4];
        int sA[4], dA[4];
#pragma unroll
        for (int i = 0; i < 4; ++i) {
            int e = eBase + ty * 4 + i;
            int s, d;
            if (is32) { s = e32[e]; d = e32[EE + e]; }
            else      { s = (int)ei[e]; d = (int)ei[EE + e]; }
            sA[i] = s; dA[i] = d;
            float4 tu4 = *(const float4*)(g_tu + (size_t)s * 64 + tx * 4);
            float4 tv4 = *(const float4*)(g_tv + (size_t)d * 64 + tx * 4);
            float h0 = fmaxf(acc[i][0] + tu4.x + tv4.x + b1r[0], 0.f);
            float h1 = fmaxf(acc[i][1] + tu4.y + tv4.y + b1r[1], 0.f);
            float h2 = fmaxf(acc[i][2] + tu4.z + tv4.z + b1r[2], 0.f);
            float h3 = fmaxf(acc[i][3] + tu4.w + tv4.w + b1r[3], 0.f);
            gp[i] = h0 * w2r[0] + h1 * w2r[1] + h2 * w2r[2] + h3 * w2r[3];
        }
#pragma unroll
        for (int off = 8; off; off >>= 1) {
#pragma unroll
            for (int i = 0; i < 4; ++i)
                gp[i] += __shfl_xor_sync(0xffffffffu, gp[i], off);
        }
        if (tx == 0) {
#pragma unroll
            for (int i = 0; i < 4; ++i) {
                int e = eBase + ty * 4 + i;
                float gate = 1.f / (1.f + expf(-(gp[i] + b2s)));
                g_gate[e] = gate;
                g_src[e] = sA[i];
                g_dst[e] = dA[i];
                atomicAdd(&g_deg[dA[i]], gate);
                atomicAdd(&g_cnt[dA[i]], 1);
            }
        }
        __syncthreads();   // protect sF before next tile's writes
    }
}

// ---------------- prefix scan of counts -> row_ptr (3 kernels) ----------------
__global__ __launch_bounds__(1024) void k_scan1() {
    __shared__ int sh[1024];
    int t = threadIdx.x;
    int i = blockIdx.x * 1024 + t;
    int v = (i < NN) ? g_cnt[i] : 0;
    sh[t] = v; __syncthreads();
#pragma unroll
    for (int off = 1; off < 1024; off <<= 1) {
        int x = (t >= off) ? sh[t - off] : 0;
        __syncthreads();
        sh[t] += x;
        __syncthreads();
    }
    if (i < NN) g_tmp[i] = sh[t];
    if (t == 1023) g_bsum[blockIdx.x] = sh[1023];
}

__global__ __launch_bounds__(128) void k_scan2() {
    __shared__ int sh[128];
    int t = threadIdx.x;
    int v = (t < NB_SCAN) ? g_bsum[t] : 0;
    sh[t] = v; __syncthreads();
#pragma unroll
    for (int off = 1; off < 128; off <<= 1) {
        int x = (t >= off) ? sh[t - off] : 0;
        __syncthreads();
        sh[t] += x;
        __syncthreads();
    }
    if (t < NB_SCAN) g_bsum2[t] = sh[t];
}

__global__ void k_scan3() {
    int i = blockIdx.x * 256 + threadIdx.x;
    if (i >= NN) return;
    int b = i >> 10;
    int off = b ? g_bsum2[b - 1] : 0;
    int excl = g_tmp[i] - g_cnt[i] + off;
    g_rowptr[i] = excl;
    g_cursor[i] = excl;
    if (i == 0) g_rowptr[NN] = EE;
}

// ---------------- dinv ----------------
__global__ void k_dinv() {
    int i = blockIdx.x * 256 + threadIdx.x;
    if (i < NN) g_dinv[i] = rsqrtf(g_deg[i]);
}

// ---------------- fill CSR (norm + src, bucketed by dst) ----------------
__global__ void k_fill() {
    int e = blockIdx.x * 256 + threadIdx.x;
    if (e >= EE) return;
    int s = g_src[e], d = g_dst[e];
    float nrm = g_dinv[s] * g_gate[e] * g_dinv[d];
    int p = atomicAdd(&g_cursor[d], 1);
    g_csr_src[p] = s;
    g_csr_norm[p] = nrm;
}

// ---------------- SGEMM: C[M,BN] = A[M,128] @ B[128,BN] (+bias) ----------------
template <int BN, bool ADD_BIAS>
__global__ __launch_bounds__(256) void k_gemm2(const float* __restrict__ A,
                                               const float* __restrict__ B,
                                               const float* __restrict__ bias,
                                               float* __restrict__ C, int M) {
    constexpr int TN = BN / 16;   // 8 for 128, 4 for 64
    __shared__ __align__(16) float As[16][132];
    __shared__ __align__(16) float Bs[16][BN];

    int tid = threadIdx.x;
    int tx = tid & 15, ty = tid >> 4;
    int rowBase = blockIdx.x * 128;

    float acc[8][TN];
#pragma unroll
    for (int m = 0; m < 8; ++m)
#pragma unroll
        for (int n = 0; n < TN; ++n) acc[m][n] = 0.f;

    int ar = tid >> 1;            // 0..127
    int ak = (tid & 1) * 8;       // 0 or 8

    for (int k0 = 0; k0 < 128; k0 += 16) {
        float4 a0 = make_float4(0.f,0.f,0.f,0.f), a1 = a0;
        int grow = rowBase + ar;
        if (grow < M) {
            a0 = *(const float4*)(A + (size_t)grow * 128 + k0 + ak);
            a1 = *(const float4*)(A + (size_t)grow * 128 + k0 + ak + 4);
        }
        As[ak + 0][ar] = a0.x; As[ak + 1][ar] = a0.y;
        As[ak + 2][ar] = a0.z; As[ak + 3][ar] = a0.w;
        As[ak + 4][ar] = a1.x; As[ak + 5][ar] = a1.y;
        As[ak + 6][ar] = a1.z; As[ak + 7][ar] = a1.w;

        if (BN == 128) {
            int br = tid >> 5, bc = (tid & 31) * 4;
            *(float4*)&Bs[br][bc]     = *(const float4*)(B + (size_t)(k0 + br) * BN + bc);
            *(float4*)&Bs[br + 8][bc] = *(const float4*)(B + (size_t)(k0 + br + 8) * BN + bc);
        } else {
            int br = tid >> 4, bc = (tid & 15) * 4;
            *(float4*)&Bs[br][bc] = *(const float4*)(B + (size_t)(k0 + br) * BN + bc);
        }
        __syncthreads();

#pragma unroll
        for (int k = 0; k < 16; ++k) {
            float a[8], bb[TN];
            float4 av0 = *(const float4*)&As[k][ty * 4];
            float4 av1 = *(const float4*)&As[k][ty * 4 + 64];
            a[0]=av0.x; a[1]=av0.y; a[2]=av0.z; a[3]=av0.w;
            a[4]=av1.x; a[5]=av1.y; a[6]=av1.z; a[7]=av1.w;
            float4 bv0 = *(const float4*)&Bs[k][tx * 4];
            bb[0]=bv0.x; bb[1]=bv0.y; bb[2]=bv0.z; bb[3]=bv0.w;
            if (TN == 8) {
                float4 bv1 = *(const float4*)&Bs[k][tx * 4 + 64];
                bb[4]=bv1.x; bb[5]=bv1.y; bb[6]=bv1.z; bb[7]=bv1.w;
            }
#pragma unroll
            for (int m = 0; m < 8; ++m)
#pragma unroll
                for (int n = 0; n < TN; ++n) acc[m][n] += a[m] * bb[n];
        }
        __syncthreads();
    }

#pragma unroll
    for (int m = 0; m < 8; ++m) {
        int r = rowBase + ty * 4 + ((m < 4) ? m : (64 + m - 4));
        if (r < M) {
            float4 v = make_float4(acc[m][0], acc[m][1], acc[m][2], acc[m][3]);
            if (ADD_BIAS) {
                v.x += bias[tx*4+0]; v.y += bias[tx*4+1];
                v.z += bias[tx*4+2]; v.w += bias[tx*4+3];
            }
            *(float4*)(C + (size_t)r * BN + tx * 4) = v;
            if (TN == 8) {
                float4 v2 = make_float4(acc[m][4], acc[m][5], acc[m][6], acc[m][7]);
                if (ADD_BIAS) {
                    v2.x += bias[tx*4+64]; v2.y += bias[tx*4+65];
                    v2.z += bias[tx*4+66]; v2.w += bias[tx*4+67];
                }
                *(float4*)(C + (size_t)r * BN + tx * 4 + 64) = v2;
            }
        }
    }
}

// ---------------- fused aggregate + bias + LN + relu + residual (warp/node) ----------------
__global__ __launch_bounds__(256) void k_agg(const float* __restrict__ xin,
                                             float* __restrict__ xout,
                                             const float* __restrict__ cb,
                                             const float* __restrict__ lg,
                                             const float* __restrict__ lb) {
    int w = (blockIdx.x * 256 + threadIdx.x) >> 5;
    int lane = threadIdx.x & 31;
    if (w >= NN) return;

    int base = g_rowptr[w], end = g_rowptr[w + 1];
    float di = g_dinv[w];
    float sw = di * di;
    float4 acc = *(const float4*)(g_xw + (size_t)w * 128 + lane * 4);
    acc.x *= sw; acc.y *= sw; acc.z *= sw; acc.w *= sw;

    int i = base, s = 0;
    float nrm = 0.f;
    if (i < end) { s = g_csr_src[i]; nrm = g_csr_norm[i]; }
    while (i < end) {
        float4 v = *(const float4*)(g_xw + (size_t)s * 128 + lane * 4);
        int i2 = i + 1, s2 = 0;
        float n2 = 0.f;
        if (i2 < end) { s2 = g_csr_src[i2]; n2 = g_csr_norm[i2]; }
        acc.x += nrm * v.x; acc.y += nrm * v.y;
        acc.z += nrm * v.z; acc.w += nrm * v.w;
        i = i2; s = s2; nrm = n2;
    }

    float4 b = *(const float4*)(cb + lane * 4);
    acc.x += b.x; acc.y += b.y; acc.z += b.z; acc.w += b.w;

    float ssum = acc.x + acc.y + acc.z + acc.w;
#pragma unroll
    for (int o = 16; o; o >>= 1) ssum += __shfl_xor_sync(0xffffffffu, ssum, o);
    float mean = ssum * 0.0078125f;
    float d0 = acc.x - mean, d1 = acc.y - mean, d2 = acc.z - mean, d3 = acc.w - mean;
    float ss = d0*d0 + d1*d1 + d2*d2 + d3*d3;
#pragma unroll
    for (int o = 16; o; o >>= 1) ss += __shfl_xor_sync(0xffffffffu, ss, o);
    float inv = rsqrtf(ss * 0.0078125f + 1e-5f);

    float4 g = *(const float4*)(lg + lane * 4);
    float4 bb = *(const float4*)(lb + lane * 4);
    float4 xi = *(const float4*)(xin + (size_t)w * 128 + lane * 4);
    float4 o4;
    o4.x = xi.x + fmaxf(d0 * inv * g.x + bb.x, 0.f);
    o4.y = xi.y + fmaxf(d1 * inv * g.y + bb.y, 0.f);
    o4.z = xi.z + fmaxf(d2 * inv * g.z + bb.z, 0.f);
    o4.w = xi.w + fmaxf(d3 * inv * g.w + bb.w, 0.f);
    *(float4*)(xout + (size_t)w * 128 + lane * 4) = o4;
}

// ---------------- orchestration ----------------
extern "C" void kernel_launch(void* const* d_in, const int* in_sizes, int n_in,
                              void* d_out, int out_size) {
    const float*     x     = (const float*)d_in[0];
    const float*     motif = (const float*)d_in[1];
    const long long* ei    = (const long long*)d_in[2];
    const float*     gw1   = (const float*)d_in[3];
    const float*     gb1   = (const float*)d_in[4];
    const float*     gw2   = (const float*)d_in[5];
    const float*     gb2   = (const float*)d_in[6];
    const float*     cw    = (const float*)d_in[7];
    const float*     cb    = (const float*)d_in[8];
    const float*     lg    = (const float*)d_in[9];
    const float*     lb    = (const float*)d_in[10];
    const float*     hw    = (const float*)d_in[11];
    const float*     hb    = (const float*)d_in[12];
    float* out = (float*)d_out;

    float *x1p, *xwp;
    cudaGetSymbolAddress((void**)&x1p, g_x1);
    cudaGetSymbolAddress((void**)&xwp, g_xw);

    k_detect<<<1, 32>>>(ei);
    k_init<<<(NN + 255) / 256, 256>>>();
    k_node_pre<<<(NN + 127) / 128, 128>>>(motif, gw1);
    k_edge_gate<<<1184, 256>>>(ei, motif, gw1, gb1, gw2, gb2);
    k_scan1<<<NB_SCAN, 1024>>>();
    k_scan2<<<1, 128>>>();
    k_scan3<<<(NN + 255) / 256, 256>>>();
    k_dinv<<<(NN + 255) / 256, 256>>>();
    k_fill<<<EE / 256, 256>>>();

    for (int i = 0; i < 2; ++i) {
        const float* xin = (i == 0) ? x : x1p;
        k_gemm2<128, false><<<(NN + 127) / 128, 256>>>(xin, cw + i * 128 * 128, nullptr, xwp, NN);
        k_agg<<<(NN + 7) / 8, 256>>>(xin, x1p, cb + i * 128, lg + i * 128, lb + i * 128);
    }
    k_gemm2<64, true><<<(NN + 127) / 128, 256>>>(x1p, hw, hb, out, NN);
}